// round 1
// baseline (speedup 1.0000x reference)
#include <cuda_runtime.h>

// Problem constants (fixed shapes for this problem instance)
#define C_ATOM 128
#define C_REF  389
#define C_PAIR 16

// ---------------------------------------------------------------------------
// Kernel 1: cl = feats @ W_feats + b_feats
// feats[n] = [pos(3), charge(1), mask(1), element(128), names_flat(256)]
// Block: 128 threads (one per output channel), ROWS=8 rows per block.
// ---------------------------------------------------------------------------
__global__ void cl_kernel(const float* __restrict__ pos,
                          const float* __restrict__ charge,
                          const float* __restrict__ mask,
                          const float* __restrict__ elem,
                          const float* __restrict__ names,
                          const float* __restrict__ Wf,
                          const float* __restrict__ bf,
                          float* __restrict__ out, int N)
{
    const int ROWS = 8;
    __shared__ float sf[ROWS][C_REF];

    const int n0  = blockIdx.x * ROWS;
    const int tid = threadIdx.x;

    // Cooperative staging of the 8 feature rows into shared memory.
    for (int idx = tid; idx < ROWS * C_REF; idx += blockDim.x) {
        int r = idx / C_REF;
        int j = idx - r * C_REF;
        int n = n0 + r;
        float v;
        if (j < 3)        v = pos[n * 3 + j];
        else if (j == 3)  v = charge[n];
        else if (j == 4)  v = mask[n];
        else if (j < 133) v = elem[n * 128 + (j - 5)];
        else              v = names[n * 256 + (j - 133)];
        sf[r][j] = v;
    }
    __syncthreads();

    const int c = tid;  // output channel
    float acc[ROWS];
    const float b = bf[c];
#pragma unroll
    for (int r = 0; r < ROWS; r++) acc[r] = b;

#pragma unroll 4
    for (int j = 0; j < C_REF; j++) {
        const float w = Wf[j * C_ATOM + c];   // coalesced across threads
#pragma unroll
        for (int r = 0; r < ROWS; r++)
            acc[r] += sf[r][j] * w;           // sf read is a warp broadcast
    }

#pragma unroll
    for (int r = 0; r < ROWS; r++)
        out[(long long)(n0 + r) * C_ATOM + c] = acc[r];
}

// ---------------------------------------------------------------------------
// Kernel 2: plm[l][m][k] = v * (d.W_off[:,k] + inv_sq*W_inv[k]
//                               + b_off[k] + b_inv[k] + W_vm[k] + b_vm[k])
// with d = pos[l]-pos[m], v = (uid[l]==uid[m]), inv_sq = 1/(1+|d|^2).
//
// 256 threads/block; 4 threads per (l,m) pair -> 64 pairs/block.
// N % 64 == 0, so every block owns exactly one l.
// Each thread emits one float4 -> warp STG.128 covers 512B contiguous.
// ---------------------------------------------------------------------------
__global__ void plm_kernel(const float* __restrict__ pos,
                           const int*   __restrict__ uid,
                           const float* __restrict__ Woff,
                           const float* __restrict__ boff,
                           const float* __restrict__ Winv,
                           const float* __restrict__ binv,
                           const float* __restrict__ Wvm,
                           const float* __restrict__ bvm,
                           float* __restrict__ out,  // already offset to plm base
                           int N)
{
    __shared__ float w0[C_PAIR], w1[C_PAIR], w2[C_PAIR], wi[C_PAIR], cb[C_PAIR];
    __shared__ float plx, ply, plz;
    __shared__ int   ul;

    const int tid = threadIdx.x;
    const long long gbase = (long long)blockIdx.x * 64;  // first pair index
    const int l  = (int)(gbase / N);
    const int m0 = (int)(gbase - (long long)l * N);

    if (tid < C_PAIR) {
        w0[tid] = Woff[tid];
        w1[tid] = Woff[C_PAIR + tid];
        w2[tid] = Woff[2 * C_PAIR + tid];
        wi[tid] = Winv[tid];
        cb[tid] = boff[tid] + binv[tid] + Wvm[tid] + bvm[tid];
    } else if (tid == 16) {
        plx = pos[l * 3 + 0];
        ply = pos[l * 3 + 1];
        plz = pos[l * 3 + 2];
        ul  = uid[l];
    }
    __syncthreads();

    const int pair = tid >> 2;            // 0..63
    const int kg   = (tid & 3) * 4;       // k-group base: 0,4,8,12
    const int m    = m0 + pair;

    const float d0 = plx - pos[m * 3 + 0];
    const float d1 = ply - pos[m * 3 + 1];
    const float d2 = plz - pos[m * 3 + 2];
    const float v  = (ul == uid[m]) ? 1.0f : 0.0f;
    const float inv = 1.0f / (1.0f + d0 * d0 + d1 * d1 + d2 * d2);

    float4 r;
    r.x = (d0 * w0[kg + 0] + d1 * w1[kg + 0] + d2 * w2[kg + 0] + inv * wi[kg + 0] + cb[kg + 0]) * v;
    r.y = (d0 * w0[kg + 1] + d1 * w1[kg + 1] + d2 * w2[kg + 1] + inv * wi[kg + 1] + cb[kg + 1]) * v;
    r.z = (d0 * w0[kg + 2] + d1 * w1[kg + 2] + d2 * w2[kg + 2] + inv * wi[kg + 2] + cb[kg + 2]) * v;
    r.w = (d0 * w0[kg + 3] + d1 * w1[kg + 3] + d2 * w2[kg + 3] + inv * wi[kg + 3] + cb[kg + 3]) * v;

    const long long o = (gbase + pair) * C_PAIR + kg;
    *reinterpret_cast<float4*>(out + o) = r;
}

// ---------------------------------------------------------------------------
// Launch. Inputs in metadata order:
// 0 ref_pos [1,N,3] f32        1 ref_charge [1,N] f32
// 2 ref_mask [1,N] f32         3 ref_element [1,N,128] f32
// 4 ref_atom_name_chars [1,N,4,64] f32
// 5 ref_space_uid [1,N] i32
// 6 W_feats [389,128]  7 b_feats [128]
// 8 W_off [3,16]       9 b_off [16]
// 10 W_inv [1,16]      11 b_inv [16]
// 12 W_vm [1,16]       13 b_vm [16]
// Output: concat(cl [N,128], plm [N,N,16]) as f32.
// ---------------------------------------------------------------------------
extern "C" void kernel_launch(void* const* d_in, const int* in_sizes, int n_in,
                              void* d_out, int out_size)
{
    const float* pos    = (const float*)d_in[0];
    const float* charge = (const float*)d_in[1];
    const float* maskp  = (const float*)d_in[2];
    const float* elem   = (const float*)d_in[3];
    const float* names  = (const float*)d_in[4];
    const int*   uid    = (const int*)  d_in[5];
    const float* Wf     = (const float*)d_in[6];
    const float* bf     = (const float*)d_in[7];
    const float* Woff   = (const float*)d_in[8];
    const float* boff   = (const float*)d_in[9];
    const float* Winv   = (const float*)d_in[10];
    const float* binv   = (const float*)d_in[11];
    const float* Wvm    = (const float*)d_in[12];
    const float* bvm    = (const float*)d_in[13];

    const int N = in_sizes[1];  // B*N with B=1
    float* out = (float*)d_out;

    // cl: N/8 blocks x 128 threads
    cl_kernel<<<N / 8, 128>>>(pos, charge, maskp, elem, names, Wf, bf, out, N);

    // plm: (N*N/64) blocks x 256 threads, output after cl block
    const long long pairs = (long long)N * N;
    const unsigned int blocks = (unsigned int)(pairs / 64);
    plm_kernel<<<blocks, 256>>>(pos, uid, Woff, boff, Winv, binv, Wvm, bvm,
                                out + (long long)N * C_ATOM, N);
}

// round 2
// speedup vs baseline: 1.8266x; 1.8266x over previous
#include <cuda_runtime.h>

#define C_ATOM 128
#define C_REF  389
#define C_PAIR 16

// Packed (x, y, z, uid_as_float_bits) per atom. 4096 capacity (N=2048 here).
__device__ float4 g_pos4[4096];

// ---------------------------------------------------------------------------
// Kernel 0: pack pos + uid into float4 table (tiny, runs once per launch)
// ---------------------------------------------------------------------------
__global__ void pack_kernel(const float* __restrict__ pos,
                            const int* __restrict__ uid, int N)
{
    int t = blockIdx.x * blockDim.x + threadIdx.x;
    if (t < N) {
        float4 p;
        p.x = pos[t * 3 + 0];
        p.y = pos[t * 3 + 1];
        p.z = pos[t * 3 + 2];
        p.w = __int_as_float(uid[t]);
        g_pos4[t] = p;
    }
}

// ---------------------------------------------------------------------------
// Kernel 1: cl = feats @ W_feats + b_feats
// Block: 128 threads (4 warps), 8 rows per block (2 rows per warp).
// Lane owns 4 channels -> W loaded as LDG.128, coalesced 512B per warp.
// ---------------------------------------------------------------------------
__global__ void cl_kernel(const float* __restrict__ pos,
                          const float* __restrict__ charge,
                          const float* __restrict__ mask,
                          const float* __restrict__ elem,
                          const float* __restrict__ names,
                          const float* __restrict__ Wf,
                          const float* __restrict__ bf,
                          float* __restrict__ out, int N)
{
    const int ROWS = 8;
    __shared__ float sf[ROWS][C_REF];

    const int n0   = blockIdx.x * ROWS;
    const int tid  = threadIdx.x;
    const int warp = tid >> 5;
    const int lane = tid & 31;

    // Cooperative staging of 8 feature rows.
    for (int idx = tid; idx < ROWS * C_REF; idx += blockDim.x) {
        int r = idx / C_REF;
        int j = idx - r * C_REF;
        int n = n0 + r;
        float v;
        if (j < 3)        v = pos[n * 3 + j];
        else if (j == 3)  v = charge[n];
        else if (j == 4)  v = mask[n];
        else if (j < 133) v = elem[n * 128 + (j - 5)];
        else              v = names[n * 256 + (j - 133)];
        sf[r][j] = v;
    }
    __syncthreads();

    const int r0 = warp * 2;
    const int r1 = r0 + 1;
    const int c4 = lane * 4;

    float4 bias = *reinterpret_cast<const float4*>(bf + c4);
    float4 a0 = bias, a1 = bias;

#pragma unroll 4
    for (int j = 0; j < C_REF; j++) {
        float4 w = *reinterpret_cast<const float4*>(Wf + j * C_ATOM + c4);
        float f0 = sf[r0][j];
        float f1 = sf[r1][j];
        a0.x = fmaf(w.x, f0, a0.x); a0.y = fmaf(w.y, f0, a0.y);
        a0.z = fmaf(w.z, f0, a0.z); a0.w = fmaf(w.w, f0, a0.w);
        a1.x = fmaf(w.x, f1, a1.x); a1.y = fmaf(w.y, f1, a1.y);
        a1.z = fmaf(w.z, f1, a1.z); a1.w = fmaf(w.w, f1, a1.w);
    }

    *reinterpret_cast<float4*>(out + (long long)(n0 + r0) * C_ATOM + c4) = a0;
    *reinterpret_cast<float4*>(out + (long long)(n0 + r1) * C_ATOM + c4) = a1;
}

// ---------------------------------------------------------------------------
// Kernel 2: plm. 256 threads/block, 4 threads per pair, 64 pairs per iter,
// ITERS=16 iterations per block -> 1024 pairs/block (single l per block
// since 1024 divides N=2048).
// All 20 coefficient floats live in registers; geometry comes from one
// LDG.128 of the packed pos4 table (L1/L2 resident, 32 KB).
// ---------------------------------------------------------------------------
#define PLM_ITERS 16

__global__ void plm_kernel(const float* __restrict__ Woff,
                           const float* __restrict__ boff,
                           const float* __restrict__ Winv,
                           const float* __restrict__ binv,
                           const float* __restrict__ Wvm,
                           const float* __restrict__ bvm,
                           float* __restrict__ out,  // plm base
                           int N)
{
    const int tid  = threadIdx.x;
    const int pair = tid >> 2;          // 0..63
    const int kg   = (tid & 3) * 4;     // 0,4,8,12

    const long long pbase = (long long)blockIdx.x * (64 * PLM_ITERS);
    const int l  = (int)(pbase / N);
    int m        = (int)(pbase - (long long)l * N) + pair;

    // Per-thread constants (registers).
    const float4 w0 = *reinterpret_cast<const float4*>(Woff + kg);
    const float4 w1 = *reinterpret_cast<const float4*>(Woff + C_PAIR + kg);
    const float4 w2 = *reinterpret_cast<const float4*>(Woff + 2 * C_PAIR + kg);
    const float4 wi = *reinterpret_cast<const float4*>(Winv + kg);
    const float4 b1 = *reinterpret_cast<const float4*>(boff + kg);
    const float4 b2 = *reinterpret_cast<const float4*>(binv + kg);
    const float4 b3 = *reinterpret_cast<const float4*>(Wvm + kg);
    const float4 b4 = *reinterpret_cast<const float4*>(bvm + kg);
    float4 cb;
    cb.x = b1.x + b2.x + b3.x + b4.x;
    cb.y = b1.y + b2.y + b3.y + b4.y;
    cb.z = b1.z + b2.z + b3.z + b4.z;
    cb.w = b1.w + b2.w + b3.w + b4.w;

    const float4 pl = g_pos4[l];
    const int ul = __float_as_int(pl.w);

    float* op = out + (pbase + pair) * C_PAIR + kg;

#pragma unroll
    for (int it = 0; it < PLM_ITERS; it++) {
        const float4 pm = g_pos4[m];
        const float d0 = pl.x - pm.x;
        const float d1 = pl.y - pm.y;
        const float d2 = pl.z - pm.z;
        const float v  = (__float_as_int(pm.w) == ul) ? 1.0f : 0.0f;

        float s = fmaf(d0, d0, 1.0f);
        s = fmaf(d1, d1, s);
        s = fmaf(d2, d2, s);
        const float inv = __fdividef(1.0f, s);

        float4 r;
        r.x = fmaf(d0, w0.x, cb.x); r.y = fmaf(d0, w0.y, cb.y);
        r.z = fmaf(d0, w0.z, cb.z); r.w = fmaf(d0, w0.w, cb.w);
        r.x = fmaf(d1, w1.x, r.x);  r.y = fmaf(d1, w1.y, r.y);
        r.z = fmaf(d1, w1.z, r.z);  r.w = fmaf(d1, w1.w, r.w);
        r.x = fmaf(d2, w2.x, r.x);  r.y = fmaf(d2, w2.y, r.y);
        r.z = fmaf(d2, w2.z, r.z);  r.w = fmaf(d2, w2.w, r.w);
        r.x = fmaf(inv, wi.x, r.x); r.y = fmaf(inv, wi.y, r.y);
        r.z = fmaf(inv, wi.z, r.z); r.w = fmaf(inv, wi.w, r.w);
        r.x *= v; r.y *= v; r.z *= v; r.w *= v;

        __stcs(reinterpret_cast<float4*>(op), r);

        m  += 64;
        op += 64 * C_PAIR;
    }
}

// ---------------------------------------------------------------------------
// Launch.
// ---------------------------------------------------------------------------
extern "C" void kernel_launch(void* const* d_in, const int* in_sizes, int n_in,
                              void* d_out, int out_size)
{
    const float* pos    = (const float*)d_in[0];
    const float* charge = (const float*)d_in[1];
    const float* maskp  = (const float*)d_in[2];
    const float* elem   = (const float*)d_in[3];
    const float* names  = (const float*)d_in[4];
    const int*   uid    = (const int*)  d_in[5];
    const float* Wf     = (const float*)d_in[6];
    const float* bf     = (const float*)d_in[7];
    const float* Woff   = (const float*)d_in[8];
    const float* boff   = (const float*)d_in[9];
    const float* Winv   = (const float*)d_in[10];
    const float* binv   = (const float*)d_in[11];
    const float* Wvm    = (const float*)d_in[12];
    const float* bvm    = (const float*)d_in[13];

    const int N = in_sizes[1];  // B*N with B=1
    float* out = (float*)d_out;

    pack_kernel<<<(N + 255) / 256, 256>>>(pos, uid, N);

    cl_kernel<<<N / 8, 128>>>(pos, charge, maskp, elem, names, Wf, bf, out, N);

    const long long pairs = (long long)N * N;
    const unsigned int blocks = (unsigned int)(pairs / (64 * PLM_ITERS));
    plm_kernel<<<blocks, 256>>>(Woff, boff, Winv, binv, Wvm, bvm,
                                out + (long long)N * C_ATOM, N);
}

// round 3
// speedup vs baseline: 2.6558x; 1.4539x over previous
#include <cuda_runtime.h>

#define C_ATOM 128
#define C_REF  389
#define C_PAIR 16

#define PLM_ITERS 16
#define PAIRS_PER_ITER 64          // 256 threads / 4 threads-per-pair
#define PAIRS_PER_BLOCK (PLM_ITERS * PAIRS_PER_ITER)  // 1024
#define CL_ROWS 16                 // rows per cl block (8 warps x 2 rows)

// ---------------------------------------------------------------------------
// Fused kernel. Blocks [0, clBlocks) compute cl; the rest compute plm.
//
// cl:  out[n][c] = sum_j feats[n][j] * Wf[j][c] + bf[c]
//      256 threads = 8 warps; warp owns 2 rows; lane owns 4 channels (LDG.128
//      on W, coalesced 512B/warp); feature rows staged in shared (broadcast).
//
// plm: out2[l][m][k] = v * (d.Woff[:,k] + inv*Winv[k] + boff+binv+Wvm+bvm)[k]
//      v = (uid[l]==uid[m]); ~99.6% of pairs have v=0 -> store exact zeros
//      without touching pos or the FMA pipe. 4 threads/pair, each stores one
//      float4 -> every warp STG.128 covers 512B contiguous.
// ---------------------------------------------------------------------------
__global__ void __launch_bounds__(256)
fused_kernel(const float* __restrict__ pos,
             const float* __restrict__ charge,
             const float* __restrict__ mask,
             const float* __restrict__ elem,
             const float* __restrict__ names,
             const int*   __restrict__ uid,
             const float* __restrict__ Wf,
             const float* __restrict__ bf,
             const float* __restrict__ Woff,
             const float* __restrict__ boff,
             const float* __restrict__ Winv,
             const float* __restrict__ binv,
             const float* __restrict__ Wvm,
             const float* __restrict__ bvm,
             float* __restrict__ out, int N, int clBlocks)
{
    __shared__ float sf[CL_ROWS][C_REF];

    const int tid = threadIdx.x;

    if (blockIdx.x < clBlocks) {
        // ------------------------- cl path ---------------------------------
        const int n0   = blockIdx.x * CL_ROWS;
        const int warp = tid >> 5;
        const int lane = tid & 31;

        for (int idx = tid; idx < CL_ROWS * C_REF; idx += 256) {
            int r = idx / C_REF;
            int j = idx - r * C_REF;
            int n = n0 + r;
            float v;
            if (j < 3)        v = pos[n * 3 + j];
            else if (j == 3)  v = charge[n];
            else if (j == 4)  v = mask[n];
            else if (j < 133) v = elem[n * 128 + (j - 5)];
            else              v = names[n * 256 + (j - 133)];
            sf[r][j] = v;
        }
        __syncthreads();

        const int r0 = warp * 2;
        const int r1 = r0 + 1;
        const int c4 = lane * 4;

        float4 bias = *reinterpret_cast<const float4*>(bf + c4);
        float4 a0 = bias, a1 = bias;

#pragma unroll 4
        for (int j = 0; j < C_REF; j++) {
            float4 w = *reinterpret_cast<const float4*>(Wf + j * C_ATOM + c4);
            float f0 = sf[r0][j];
            float f1 = sf[r1][j];
            a0.x = fmaf(w.x, f0, a0.x); a0.y = fmaf(w.y, f0, a0.y);
            a0.z = fmaf(w.z, f0, a0.z); a0.w = fmaf(w.w, f0, a0.w);
            a1.x = fmaf(w.x, f1, a1.x); a1.y = fmaf(w.y, f1, a1.y);
            a1.z = fmaf(w.z, f1, a1.z); a1.w = fmaf(w.w, f1, a1.w);
        }

        *reinterpret_cast<float4*>(out + (long long)(n0 + r0) * C_ATOM + c4) = a0;
        *reinterpret_cast<float4*>(out + (long long)(n0 + r1) * C_ATOM + c4) = a1;
        return;
    }

    // --------------------------- plm path ----------------------------------
    const int pair = tid >> 2;           // 0..63
    const int kg   = (tid & 3) * 4;      // 0,4,8,12

    const long long pbase = (long long)(blockIdx.x - clBlocks) * PAIRS_PER_BLOCK;
    const int l = (int)(pbase / N);
    int m       = (int)(pbase - (long long)l * N) + pair;

    // Coefficients in registers (per-thread, reused across 16 iters).
    const float4 w0 = *reinterpret_cast<const float4*>(Woff + kg);
    const float4 w1 = *reinterpret_cast<const float4*>(Woff + C_PAIR + kg);
    const float4 w2 = *reinterpret_cast<const float4*>(Woff + 2 * C_PAIR + kg);
    const float4 wi = *reinterpret_cast<const float4*>(Winv + kg);
    float4 cb;
    {
        const float4 t1 = *reinterpret_cast<const float4*>(boff + kg);
        const float4 t2 = *reinterpret_cast<const float4*>(binv + kg);
        const float4 t3 = *reinterpret_cast<const float4*>(Wvm + kg);
        const float4 t4 = *reinterpret_cast<const float4*>(bvm + kg);
        cb.x = t1.x + t2.x + t3.x + t4.x;
        cb.y = t1.y + t2.y + t3.y + t4.y;
        cb.z = t1.z + t2.z + t3.z + t4.z;
        cb.w = t1.w + t2.w + t3.w + t4.w;
    }

    const int   ul  = __ldg(uid + l);
    const float plx = __ldg(pos + l * 3 + 0);
    const float ply = __ldg(pos + l * 3 + 1);
    const float plz = __ldg(pos + l * 3 + 2);

    float* op = out + (long long)N * C_ATOM + (pbase + pair) * C_PAIR + kg;

#pragma unroll
    for (int it = 0; it < PLM_ITERS; it++) {
        const int um = __ldg(uid + m);
        float4 r;
        if (um == ul) {
            // Rare path (~0.4% of pairs): full affine map.
            const float d0 = plx - __ldg(pos + m * 3 + 0);
            const float d1 = ply - __ldg(pos + m * 3 + 1);
            const float d2 = plz - __ldg(pos + m * 3 + 2);
            float s = fmaf(d0, d0, 1.0f);
            s = fmaf(d1, d1, s);
            s = fmaf(d2, d2, s);
            const float inv = __fdividef(1.0f, s);

            r.x = fmaf(d0, w0.x, cb.x); r.y = fmaf(d0, w0.y, cb.y);
            r.z = fmaf(d0, w0.z, cb.z); r.w = fmaf(d0, w0.w, cb.w);
            r.x = fmaf(d1, w1.x, r.x);  r.y = fmaf(d1, w1.y, r.y);
            r.z = fmaf(d1, w1.z, r.z);  r.w = fmaf(d1, w1.w, r.w);
            r.x = fmaf(d2, w2.x, r.x);  r.y = fmaf(d2, w2.y, r.y);
            r.z = fmaf(d2, w2.z, r.z);  r.w = fmaf(d2, w2.w, r.w);
            r.x = fmaf(inv, wi.x, r.x); r.y = fmaf(inv, wi.y, r.y);
            r.z = fmaf(inv, wi.z, r.z); r.w = fmaf(inv, wi.w, r.w);
        } else {
            // Dominant path: exact zero (reference multiplies every term by v=0).
            r = make_float4(0.f, 0.f, 0.f, 0.f);
        }
        __stcs(reinterpret_cast<float4*>(op), r);

        m  += PAIRS_PER_ITER;
        op += PAIRS_PER_ITER * C_PAIR;
    }
}

// ---------------------------------------------------------------------------
// Launch.
// ---------------------------------------------------------------------------
extern "C" void kernel_launch(void* const* d_in, const int* in_sizes, int n_in,
                              void* d_out, int out_size)
{
    const float* pos    = (const float*)d_in[0];
    const float* charge = (const float*)d_in[1];
    const float* maskp  = (const float*)d_in[2];
    const float* elem   = (const float*)d_in[3];
    const float* names  = (const float*)d_in[4];
    const int*   uid    = (const int*)  d_in[5];
    const float* Wf     = (const float*)d_in[6];
    const float* bf     = (const float*)d_in[7];
    const float* Woff   = (const float*)d_in[8];
    const float* boff   = (const float*)d_in[9];
    const float* Winv   = (const float*)d_in[10];
    const float* binv   = (const float*)d_in[11];
    const float* Wvm    = (const float*)d_in[12];
    const float* bvm    = (const float*)d_in[13];

    const int N = in_sizes[1];  // B*N with B=1
    float* out = (float*)d_out;

    const int clBlocks  = N / CL_ROWS;                       // 128
    const long long pairs = (long long)N * N;
    const unsigned int plmBlocks = (unsigned int)(pairs / PAIRS_PER_BLOCK);  // 4096

    fused_kernel<<<clBlocks + plmBlocks, 256>>>(
        pos, charge, maskp, elem, names, uid, Wf, bf,
        Woff, boff, Winv, binv, Wvm, bvm, out, N, clBlocks);
}